// round 2
// baseline (speedup 1.0000x reference)
#include <cuda_runtime.h>
#include <cstdint>

#define NN  100000
#define EE  1600000
#define FIN 256
#define HD  128
#define CC  16

// Scratch (static device globals -- no allocation in kernel_launch)
__device__ int   g_deg[NN];
__device__ float g_dinv[NN];
__device__ float g_h2 [(size_t)NN * HD];   // h * dinv[row]  (gather source)
__device__ float g_acc[(size_t)NN * HD];   // initialized to h2, scatter target
__device__ float g_w  [CC * HD];
__device__ float g_b  [CC];
__device__ int   g_i64;                    // 1 if edge_index is int64, else int32

// ---------------------------------------------------------------------------
// Detect edge_index dtype: if int64 (little-endian, values < 2^31), every
// odd 32-bit word of the first 1024 elements is zero. For int32 data those
// words are random values in [0, N) -- all-zero is probability ~0.
// ---------------------------------------------------------------------------
__global__ void __launch_bounds__(256) k_detect(const unsigned int* __restrict__ w) {
    __shared__ unsigned int s[256];
    int tx = threadIdx.x;
    unsigned int acc = 0;
    #pragma unroll
    for (int i = tx; i < 1024; i += 256) acc |= w[2 * i + 1];
    s[tx] = acc;
    __syncthreads();
    for (int o = 128; o; o >>= 1) {
        if (tx < o) s[tx] |= s[tx + o];
        __syncthreads();
    }
    if (tx == 0) g_i64 = (s[0] == 0u) ? 1 : 0;
}

__device__ __forceinline__ int load_idx(const void* ei, size_t i) {
    return g_i64 ? (int)((const long long*)ei)[i] : ((const int*)ei)[i];
}

// ---------------------------------------------------------------------------
// Degree / normalization
// ---------------------------------------------------------------------------
__global__ void k_deg_init(int n) {
    int i = blockIdx.x * blockDim.x + threadIdx.x;
    if (i < n) g_deg[i] = 1;                      // self-loop
}

__global__ void k_deg_count(const void* __restrict__ ei, int e) {
    int i = blockIdx.x * blockDim.x + threadIdx.x;
    if (i < e) atomicAdd(&g_deg[load_idx(ei, (size_t)e + i)], 1);
}

__global__ void k_dinv(int n) {
    int i = blockIdx.x * blockDim.x + threadIdx.x;
    if (i < n) g_dinv[i] = rsqrtf((float)g_deg[i]);
}

// ---------------------------------------------------------------------------
// Bayesian weight sampling: w = mu + exp(log_sigma) * eps
// ---------------------------------------------------------------------------
__global__ void k_wb(const float* __restrict__ wmu, const float* __restrict__ wls,
                     const float* __restrict__ bmu, const float* __restrict__ bls,
                     const float* __restrict__ ew,  const float* __restrict__ eb) {
    int tx = threadIdx.x;
    for (int i = tx; i < CC * HD; i += blockDim.x)
        g_w[i] = wmu[i] + expf(wls[i]) * ew[i];
    if (tx < CC)
        g_b[tx] = bmu[tx] + expf(bls[tx]) * eb[tx];
}

// ---------------------------------------------------------------------------
// GEMM: h2[row] = (x[row] @ W) * dinv[row]; also acc[row] = h2[row]
// Block: 64 rows x 128 cols, 256 threads, thread tile 8 rows x 4 cols.
// ---------------------------------------------------------------------------
__global__ void __launch_bounds__(256) k_gemm(const float* __restrict__ x,
                                              const float* __restrict__ W,
                                              int n) {
    __shared__ float xs[64][64];    // [row][k]
    __shared__ float Ws[64][128];   // [k][col]

    const int tx   = threadIdx.x;
    const int row0 = blockIdx.x * 64;
    const int c0   = (tx & 31) * 4;   // cols c0..c0+3
    const int r0   = (tx >> 5) * 8;   // rows r0..r0+7

    float a[8][4];
    #pragma unroll
    for (int r = 0; r < 8; r++)
        #pragma unroll
        for (int c = 0; c < 4; c++) a[r][c] = 0.f;

    for (int kk = 0; kk < FIN; kk += 64) {
        #pragma unroll
        for (int i = 0; i < 16; i++) {
            int idx = tx + i * 256;
            int r = idx >> 6, k = idx & 63;
            int gr = row0 + r;
            xs[r][k] = (gr < n) ? x[(size_t)gr * FIN + kk + k] : 0.f;
        }
        #pragma unroll
        for (int i = 0; i < 32; i++) {
            int idx = tx + i * 256;
            int k = idx >> 7, c = idx & 127;
            Ws[k][c] = W[(size_t)(kk + k) * HD + c];
        }
        __syncthreads();

        #pragma unroll 8
        for (int k = 0; k < 64; k++) {
            float4 wv = *(const float4*)&Ws[k][c0];
            #pragma unroll
            for (int r = 0; r < 8; r++) {
                float xv = xs[r0 + r][k];
                a[r][0] += xv * wv.x;
                a[r][1] += xv * wv.y;
                a[r][2] += xv * wv.z;
                a[r][3] += xv * wv.w;
            }
        }
        __syncthreads();
    }

    #pragma unroll
    for (int r = 0; r < 8; r++) {
        int gr = row0 + r0 + r;
        if (gr < n) {
            float d = g_dinv[gr];
            float4 v = make_float4(a[r][0] * d, a[r][1] * d, a[r][2] * d, a[r][3] * d);
            *(float4*)&g_h2 [(size_t)gr * HD + c0] = v;
            *(float4*)&g_acc[(size_t)gr * HD + c0] = v;
        }
    }
}

// ---------------------------------------------------------------------------
// Edge scatter: acc[dst] += h2[src]   (one warp per edge, float4 per lane,
// vector reduction -- no return value, no read-modify-write in SM)
// ---------------------------------------------------------------------------
__global__ void k_edge(const void* __restrict__ ei, int e) {
    int w    = (blockIdx.x * blockDim.x + threadIdx.x) >> 5;
    int lane = threadIdx.x & 31;
    if (w >= e) return;
    int s = load_idx(ei, (size_t)w);
    int d = load_idx(ei, (size_t)e + w);
    const float4* sp = reinterpret_cast<const float4*>(g_h2 + (size_t)s * HD);
    float4 v = __ldg(sp + lane);
    float* p = g_acc + (size_t)d * HD + lane * 4;
    asm volatile("red.global.add.v4.f32 [%0], {%1, %2, %3, %4};"
                 :: "l"(p), "f"(v.x), "f"(v.y), "f"(v.z), "f"(v.w)
                 : "memory");
}

// ---------------------------------------------------------------------------
// Finalize: a = relu(dinv*acc + gcn_b); logits = a @ w^T + b; log_softmax.
// Block handles 16 nodes; thread (node, class) = (tx>>4, tx&15).
// ---------------------------------------------------------------------------
__global__ void __launch_bounds__(256) k_final(const float* __restrict__ gcn_b,
                                               float* __restrict__ out, int n) {
    __shared__ float a_s[16][132];
    __shared__ float w_s[16][132];
    __shared__ float gb[128];
    __shared__ float b_s[16];

    const int tx = threadIdx.x;

    #pragma unroll
    for (int i = 0; i < 8; i++) {
        int idx = tx + i * 256;
        w_s[idx >> 7][idx & 127] = g_w[idx];
    }
    if (tx < 128) gb[tx] = gcn_b[tx];
    if (tx < 16)  b_s[tx] = g_b[tx];

    const int n0 = blockIdx.x * 16;

    __syncthreads();

    #pragma unroll
    for (int i = 0; i < 8; i++) {
        int idx  = tx + i * 256;
        int node = idx >> 7, h = idx & 127;
        int g    = n0 + node;
        float v  = 0.f;
        if (g < n)
            v = fmaxf(g_acc[(size_t)g * HD + h] * g_dinv[g] + gb[h], 0.f);
        a_s[node][h] = v;
    }
    __syncthreads();

    const int c    = tx & 15;
    const int node = tx >> 4;

    float lg = b_s[c];
    const float4* ap = (const float4*)&a_s[node][0];
    const float4* wp = (const float4*)&w_s[c][0];
    #pragma unroll
    for (int k = 0; k < 32; k++) {
        float4 av = ap[k];
        float4 wv = wp[k];
        lg += av.x * wv.x + av.y * wv.y + av.z * wv.z + av.w * wv.w;
    }

    // log_softmax across the 16 classes living in a 16-lane group
    float m = lg;
    #pragma unroll
    for (int o = 8; o; o >>= 1) m = fmaxf(m, __shfl_xor_sync(0xffffffffu, m, o));
    float ex = expf(lg - m);
    float ss = ex;
    #pragma unroll
    for (int o = 8; o; o >>= 1) ss += __shfl_xor_sync(0xffffffffu, ss, o);

    if (n0 + node < n)
        out[(size_t)(n0 + node) * CC + c] = lg - m - logf(ss);
}

// ---------------------------------------------------------------------------
extern "C" void kernel_launch(void* const* d_in, const int* in_sizes, int n_in,
                              void* d_out, int out_size) {
    const float* x     = (const float*)d_in[0];
    const void*  ei    = d_in[1];                 // [2, E]: row0 = src, row1 = dst
    const float* W     = (const float*)d_in[2];
    const float* gcn_b = (const float*)d_in[3];
    const float* w_mu  = (const float*)d_in[4];
    const float* w_ls  = (const float*)d_in[5];
    const float* b_mu  = (const float*)d_in[6];
    const float* b_ls  = (const float*)d_in[7];
    const float* eps_w = (const float*)d_in[8];
    const float* eps_b = (const float*)d_in[9];
    float* out = (float*)d_out;

    const int n = in_sizes[0] / FIN;
    const int e = in_sizes[1] / 2;

    k_detect   <<<1, 256>>>((const unsigned int*)ei);
    k_deg_init <<<(n + 255) / 256, 256>>>(n);
    k_deg_count<<<(e + 255) / 256, 256>>>(ei, e);
    k_dinv     <<<(n + 255) / 256, 256>>>(n);
    k_wb       <<<1, 256>>>(w_mu, w_ls, b_mu, b_ls, eps_w, eps_b);
    k_gemm     <<<(n + 63) / 64, 256>>>(x, W, n);
    k_edge     <<<(e + 7) / 8, 256>>>(ei, e);
    k_final    <<<(n + 15) / 16, 256>>>(gcn_b, out, n);
}

// round 3
// speedup vs baseline: 1.3266x; 1.3266x over previous
#include <cuda_runtime.h>
#include <cstdint>

#define NN  100000
#define EE  1600000
#define FIN 256
#define HD  128
#define CC  16
#define NB  ((NN + 511) / 512)   // scan blocks = 196

// Scratch (static device globals -- no allocation in kernel_launch)
__device__ int   g_cnt [NN];         // in-degree (no self loop)
__device__ float g_dinv[NN];
__device__ int   g_off [NN + 1];     // CSR row offsets
__device__ int   g_cur [NN];         // fill cursors
__device__ int   g_csr [EE];         // src index per incoming edge, grouped by dst
__device__ int   g_bsum[NB];         // scan block sums
__device__ float g_h2 [(size_t)NN * HD];   // h * dinv[row]  (gather source)
__device__ float g_acc[(size_t)NN * HD];   // aggregation result (pre-dinv)
__device__ float g_w  [CC * HD];
__device__ float g_b  [CC];
__device__ int   g_i64;              // 1 if edge_index is int64, else int32

// ---------------------------------------------------------------------------
// Detect edge_index dtype: if int64 (little-endian, values < 2^31), every
// odd 32-bit word of the first 1024 elements is zero.
// ---------------------------------------------------------------------------
__global__ void __launch_bounds__(256) k_detect(const unsigned int* __restrict__ w) {
    __shared__ unsigned int s[256];
    int tx = threadIdx.x;
    unsigned int acc = 0;
    #pragma unroll
    for (int i = tx; i < 1024; i += 256) acc |= w[2 * i + 1];
    s[tx] = acc;
    __syncthreads();
    for (int o = 128; o; o >>= 1) {
        if (tx < o) s[tx] |= s[tx + o];
        __syncthreads();
    }
    if (tx == 0) g_i64 = (s[0] == 0u) ? 1 : 0;
}

__device__ __forceinline__ int load_idx(const void* ei, size_t i) {
    return g_i64 ? (int)((const long long*)ei)[i] : ((const int*)ei)[i];
}

// ---------------------------------------------------------------------------
// Degree count + normalization
// ---------------------------------------------------------------------------
__global__ void k_cnt_init(int n) {
    int i = blockIdx.x * blockDim.x + threadIdx.x;
    if (i < n) g_cnt[i] = 0;
}

__global__ void k_cnt(const void* __restrict__ ei, int e) {
    int i = blockIdx.x * blockDim.x + threadIdx.x;
    if (i < e) atomicAdd(&g_cnt[load_idx(ei, (size_t)e + i)], 1);
}

__global__ void k_dinv(int n) {
    int i = blockIdx.x * blockDim.x + threadIdx.x;
    if (i < n) g_dinv[i] = rsqrtf((float)(g_cnt[i] + 1));   // +1 self loop
}

// ---------------------------------------------------------------------------
// 3-phase exclusive scan of g_cnt -> g_off / g_cur
// ---------------------------------------------------------------------------
__global__ void __launch_bounds__(512) k_scan1(int n) {
    __shared__ int s[512];
    int b = blockIdx.x, tx = threadIdx.x;
    int i = b * 512 + tx;
    s[tx] = (i < n) ? g_cnt[i] : 0;
    __syncthreads();
    for (int o = 256; o; o >>= 1) {
        if (tx < o) s[tx] += s[tx + o];
        __syncthreads();
    }
    if (tx == 0) g_bsum[b] = s[0];
}

__global__ void k_scan2(int n, int e) {
    if (threadIdx.x == 0) {
        int run = 0;
        for (int b = 0; b < NB; b++) {
            int v = g_bsum[b];
            g_bsum[b] = run;
            run += v;
        }
        g_off[n] = e;
    }
}

__global__ void __launch_bounds__(512) k_scan3(int n) {
    __shared__ int s[512];
    int b = blockIdx.x, tx = threadIdx.x;
    int i = b * 512 + tx;
    int v = (i < n) ? g_cnt[i] : 0;
    s[tx] = v;
    __syncthreads();
    #pragma unroll
    for (int o = 1; o < 512; o <<= 1) {
        int t = (tx >= o) ? s[tx - o] : 0;
        __syncthreads();
        s[tx] += t;
        __syncthreads();
    }
    if (i < n) {
        int excl = s[tx] - v + g_bsum[b];
        g_off[i] = excl;
        g_cur[i] = excl;
    }
}

// ---------------------------------------------------------------------------
// CSR fill: bucket each edge's src under its dst
// ---------------------------------------------------------------------------
__global__ void k_fill(const void* __restrict__ ei, int e) {
    int i = blockIdx.x * blockDim.x + threadIdx.x;
    if (i >= e) return;
    int s = load_idx(ei, (size_t)i);
    int d = load_idx(ei, (size_t)e + i);
    int p = atomicAdd(&g_cur[d], 1);
    g_csr[p] = s;
}

// ---------------------------------------------------------------------------
// Bayesian weight sampling: w = mu + exp(log_sigma) * eps
// ---------------------------------------------------------------------------
__global__ void k_wb(const float* __restrict__ wmu, const float* __restrict__ wls,
                     const float* __restrict__ bmu, const float* __restrict__ bls,
                     const float* __restrict__ ew,  const float* __restrict__ eb) {
    int tx = threadIdx.x;
    for (int i = tx; i < CC * HD; i += blockDim.x)
        g_w[i] = wmu[i] + expf(wls[i]) * ew[i];
    if (tx < CC)
        g_b[tx] = bmu[tx] + expf(bls[tx]) * eb[tx];
}

// ---------------------------------------------------------------------------
// GEMM: h2[row] = (x[row] @ W) * dinv[row]
// Block: 64 rows x 128 cols, 256 threads, thread tile 8 rows x 4 cols.
// ---------------------------------------------------------------------------
__global__ void __launch_bounds__(256) k_gemm(const float* __restrict__ x,
                                              const float* __restrict__ W,
                                              int n) {
    __shared__ float xs[64][64];    // [row][k]
    __shared__ float Ws[64][128];   // [k][col]

    const int tx   = threadIdx.x;
    const int row0 = blockIdx.x * 64;
    const int c0   = (tx & 31) * 4;   // cols c0..c0+3
    const int r0   = (tx >> 5) * 8;   // rows r0..r0+7

    float a[8][4];
    #pragma unroll
    for (int r = 0; r < 8; r++)
        #pragma unroll
        for (int c = 0; c < 4; c++) a[r][c] = 0.f;

    for (int kk = 0; kk < FIN; kk += 64) {
        #pragma unroll
        for (int i = 0; i < 16; i++) {
            int idx = tx + i * 256;
            int r = idx >> 6, k = idx & 63;
            int gr = row0 + r;
            xs[r][k] = (gr < n) ? x[(size_t)gr * FIN + kk + k] : 0.f;
        }
        #pragma unroll
        for (int i = 0; i < 32; i++) {
            int idx = tx + i * 256;
            int k = idx >> 7, c = idx & 127;
            Ws[k][c] = W[(size_t)(kk + k) * HD + c];
        }
        __syncthreads();

        #pragma unroll 8
        for (int k = 0; k < 64; k++) {
            float4 wv = *(const float4*)&Ws[k][c0];
            #pragma unroll
            for (int r = 0; r < 8; r++) {
                float xv = xs[r0 + r][k];
                a[r][0] += xv * wv.x;
                a[r][1] += xv * wv.y;
                a[r][2] += xv * wv.z;
                a[r][3] += xv * wv.w;
            }
        }
        __syncthreads();
    }

    #pragma unroll
    for (int r = 0; r < 8; r++) {
        int gr = row0 + r0 + r;
        if (gr < n) {
            float d = g_dinv[gr];
            float4 v = make_float4(a[r][0] * d, a[r][1] * d, a[r][2] * d, a[r][3] * d);
            *(float4*)&g_h2[(size_t)gr * HD + c0] = v;
        }
    }
}

// ---------------------------------------------------------------------------
// Aggregation (gather): acc[v] = h2[v] + sum_{e: dst=v} h2[csr[e]]
// One warp per node; lane owns one float4 (4 of the 128 cols).
// ---------------------------------------------------------------------------
__global__ void __launch_bounds__(256) k_agg(int n) {
    int w    = (blockIdx.x * blockDim.x + threadIdx.x) >> 5;
    int lane = threadIdx.x & 31;
    if (w >= n) return;

    const float4* hp = reinterpret_cast<const float4*>(g_h2);
    float4 acc = __ldg(hp + (size_t)w * 32 + lane);   // self loop

    int e0 = g_off[w], e1 = g_off[w + 1];
    for (int base = e0; base < e1; base += 32) {
        int m   = min(32, e1 - base);
        int idx = (base + lane < e1) ? g_csr[base + lane] : 0;
        for (int j = 0; j < m; j++) {
            int s = __shfl_sync(0xffffffffu, idx, j);
            float4 v = __ldg(hp + (size_t)s * 32 + lane);
            acc.x += v.x; acc.y += v.y; acc.z += v.z; acc.w += v.w;
        }
    }
    reinterpret_cast<float4*>(g_acc)[(size_t)w * 32 + lane] = acc;
}

// ---------------------------------------------------------------------------
// Finalize: a = relu(dinv*acc + gcn_b); logits = a @ w^T + b; log_softmax.
// ---------------------------------------------------------------------------
__global__ void __launch_bounds__(256) k_final(const float* __restrict__ gcn_b,
                                               float* __restrict__ out, int n) {
    __shared__ float a_s[16][132];
    __shared__ float w_s[16][132];
    __shared__ float gb[128];
    __shared__ float b_s[16];

    const int tx = threadIdx.x;

    #pragma unroll
    for (int i = 0; i < 8; i++) {
        int idx = tx + i * 256;
        w_s[idx >> 7][idx & 127] = g_w[idx];
    }
    if (tx < 128) gb[tx] = gcn_b[tx];
    if (tx < 16)  b_s[tx] = g_b[tx];

    const int n0 = blockIdx.x * 16;

    __syncthreads();

    #pragma unroll
    for (int i = 0; i < 8; i++) {
        int idx  = tx + i * 256;
        int node = idx >> 7, h = idx & 127;
        int g    = n0 + node;
        float v  = 0.f;
        if (g < n)
            v = fmaxf(g_acc[(size_t)g * HD + h] * g_dinv[g] + gb[h], 0.f);
        a_s[node][h] = v;
    }
    __syncthreads();

    const int c    = tx & 15;
    const int node = tx >> 4;

    float lg = b_s[c];
    const float4* ap = (const float4*)&a_s[node][0];
    const float4* wp = (const float4*)&w_s[c][0];
    #pragma unroll
    for (int k = 0; k < 32; k++) {
        float4 av = ap[k];
        float4 wv = wp[k];
        lg += av.x * wv.x + av.y * wv.y + av.z * wv.z + av.w * wv.w;
    }

    float m = lg;
    #pragma unroll
    for (int o = 8; o; o >>= 1) m = fmaxf(m, __shfl_xor_sync(0xffffffffu, m, o));
    float ex = expf(lg - m);
    float ss = ex;
    #pragma unroll
    for (int o = 8; o; o >>= 1) ss += __shfl_xor_sync(0xffffffffu, ss, o);

    if (n0 + node < n)
        out[(size_t)(n0 + node) * CC + c] = lg - m - logf(ss);
}

// ---------------------------------------------------------------------------
extern "C" void kernel_launch(void* const* d_in, const int* in_sizes, int n_in,
                              void* d_out, int out_size) {
    const float* x     = (const float*)d_in[0];
    const void*  ei    = d_in[1];                 // [2, E]: row0 = src, row1 = dst
    const float* W     = (const float*)d_in[2];
    const float* gcn_b = (const float*)d_in[3];
    const float* w_mu  = (const float*)d_in[4];
    const float* w_ls  = (const float*)d_in[5];
    const float* b_mu  = (const float*)d_in[6];
    const float* b_ls  = (const float*)d_in[7];
    const float* eps_w = (const float*)d_in[8];
    const float* eps_b = (const float*)d_in[9];
    float* out = (float*)d_out;

    const int n = in_sizes[0] / FIN;
    const int e = in_sizes[1] / 2;

    k_detect  <<<1, 256>>>((const unsigned int*)ei);
    k_cnt_init<<<(n + 255) / 256, 256>>>(n);
    k_cnt     <<<(e + 255) / 256, 256>>>(ei, e);
    k_dinv    <<<(n + 255) / 256, 256>>>(n);
    k_scan1   <<<NB, 512>>>(n);
    k_scan2   <<<1, 32>>>(n, e);
    k_scan3   <<<NB, 512>>>(n);
    k_fill    <<<(e + 255) / 256, 256>>>(ei, e);
    k_wb      <<<1, 256>>>(w_mu, w_ls, b_mu, b_ls, eps_w, eps_b);
    k_gemm    <<<(n + 63) / 64, 256>>>(x, W, n);
    k_agg     <<<(n * 32 + 255) / 256, 256>>>(n);
    k_final   <<<(n + 15) / 16, 256>>>(gcn_b, out, n);
}